// round 3
// baseline (speedup 1.0000x reference)
#include <cuda_runtime.h>
#include <math.h>

// Problem shapes (fixed by the dataset)
#define NN 4096          // graph nodes
#define CC 64            // input channels
#define HH 128           // embedding dim
#define NBS 48           // B*S = 4*12
#define OUT_ELEMS (48ULL * 4096ULL * 128ULL)   // 25,165,824
#define A_ELEMS   (4096ULL * 4096ULL)          // 16,777,216

// Scratch (allocation-free rule: __device__ globals)
__device__ float g_d[NN];                       // d = rsqrt(rowsum(A)+1)
__device__ float g_xemb[NBS * NN * HH];         // x_emb [bs, n, h]  (~100 MB)

// ---------------------------------------------------------------------------
// Kernel 1: row sums of A -> d[i] = (sum_k A[i,k] + 1)^-1/2
// ---------------------------------------------------------------------------
__global__ void __launch_bounds__(256) rowsum_kernel(const float* __restrict__ A) {
    int row = blockIdx.x;
    const float* a = A + (size_t)row * NN;
    float s = 0.f;
    for (int k = threadIdx.x; k < NN; k += 256) s += a[k];
    #pragma unroll
    for (int o = 16; o > 0; o >>= 1) s += __shfl_down_sync(0xffffffffu, s, o);
    __shared__ float red[8];
    if ((threadIdx.x & 31) == 0) red[threadIdx.x >> 5] = s;
    __syncthreads();
    if (threadIdx.x == 0) {
        float t = 0.f;
        #pragma unroll
        for (int w = 0; w < 8; w++) t += red[w];
        g_d[row] = rsqrtf(t + 1.0f);
    }
}

// ---------------------------------------------------------------------------
// Kernel 2: x_emb[m, h] = sum_c x[m, c] * W[h, c]    (m = bs*4096 + n)
// ---------------------------------------------------------------------------
__global__ void __launch_bounds__(256) emb_kernel(const float* __restrict__ x,
                                                  const float* __restrict__ W) {
    __shared__ float Ws[CC][HH];    // Ws[c][h] = W[h][c]   (32 KB)
    __shared__ float xs[32][CC];    // 32 rows of x         (8 KB)

    int tid = threadIdx.x;
    int m0 = blockIdx.x * 32;

    #pragma unroll
    for (int r = 0; r < 32; r++) {
        int idx = tid + 256 * r;            // idx = h*64 + c
        Ws[idx & 63][idx >> 6] = W[idx];
    }
    #pragma unroll
    for (int j = 0; j < 2; j++) {
        int q = tid + 256 * j;              // 0..511
        int r = q >> 4;                     // row 0..31
        int c4 = (q & 15) * 4;
        *(float4*)(&xs[r][c4]) =
            *(const float4*)(x + (size_t)(m0 + r) * CC + c4);
    }
    __syncthreads();

    int r  = tid >> 3;           // 0..31
    int hb = (tid & 7) * 16;     // 0..112
    float acc[16];
    #pragma unroll
    for (int j = 0; j < 16; j++) acc[j] = 0.f;

    #pragma unroll 8
    for (int c = 0; c < CC; c++) {
        float xv = xs[r][c];
        #pragma unroll
        for (int j = 0; j < 16; j++) acc[j] += xv * Ws[c][hb + j];
    }

    float* orow = g_xemb + (size_t)(m0 + r) * HH + hb;
    #pragma unroll
    for (int j4 = 0; j4 < 16; j4 += 4) {
        float4 v = make_float4(acc[j4], acc[j4+1], acc[j4+2], acc[j4+3]);
        *(float4*)(orow + j4) = v;
    }
}

// ---------------------------------------------------------------------------
// Kernel 3: main GEMM + epilogue, with register-prefetch of the next k-tile.
//   acc[i,h] = sum_k A[i,k] * (d[k] * x_emb[bs,k,h])
//   out[bs,i,h] = sigmoid(x_emb[bs,i,h] - d[i]*acc[i,h])
// 128x128 block tile, BK=8, 8x8 microtile per thread (256 threads).
// ---------------------------------------------------------------------------
__global__ void __launch_bounds__(256) gcn_gemm_kernel(const float* __restrict__ A,
                                                       float* __restrict__ out) {
    const int i0 = blockIdx.x * 128;
    const int bs = blockIdx.y;
    const float* E = g_xemb + (size_t)bs * NN * HH;

    __shared__ float As[8][128];
    __shared__ float Bs[8][128];

    const int tid = threadIdx.x;
    const int tx = tid & 15, ty = tid >> 4;
    const int ri = ty * 8, hj = tx * 8;

    // load assignments
    const int a_row = tid >> 1;          // 0..127
    const int a_k4  = (tid & 1) * 4;     // 0 or 4
    const int b_k   = tid >> 5;          // 0..7
    const int b_h   = (tid & 31) * 4;    // 0..124

    float acc[8][8];
    #pragma unroll
    for (int r = 0; r < 8; r++)
        #pragma unroll
        for (int c = 0; c < 8; c++) acc[r][c] = 0.f;

    const float* Arow = A + (size_t)(i0 + a_row) * NN + a_k4;
    const float* Brow = E + (size_t)b_k * HH + b_h;

    // prefetch tile 0 into registers
    float4 av = *(const float4*)(Arow);
    float  dk = g_d[b_k];
    float4 bv = *(const float4*)(Brow);

    for (int k0 = 0; k0 < NN; k0 += 8) {
        // store current tile to smem
        As[a_k4 + 0][a_row] = av.x;
        As[a_k4 + 1][a_row] = av.y;
        As[a_k4 + 2][a_row] = av.z;
        As[a_k4 + 3][a_row] = av.w;
        bv.x *= dk; bv.y *= dk; bv.z *= dk; bv.w *= dk;
        *(float4*)(&Bs[b_k][b_h]) = bv;
        __syncthreads();

        // prefetch next tile into registers (hidden under the FFMA block)
        if (k0 + 8 < NN) {
            av = *(const float4*)(Arow + k0 + 8);
            dk = g_d[k0 + 8 + b_k];
            bv = *(const float4*)(Brow + (size_t)(k0 + 8) * HH);
        }

        #pragma unroll
        for (int k = 0; k < 8; k++) {
            float a[8], b[8];
            *(float4*)(a)     = *(const float4*)(&As[k][ri]);
            *(float4*)(a + 4) = *(const float4*)(&As[k][ri + 4]);
            *(float4*)(b)     = *(const float4*)(&Bs[k][hj]);
            *(float4*)(b + 4) = *(const float4*)(&Bs[k][hj + 4]);
            #pragma unroll
            for (int r = 0; r < 8; r++)
                #pragma unroll
                for (int c = 0; c < 8; c++)
                    acc[r][c] += a[r] * b[c];
        }
        __syncthreads();
    }

    // epilogue: sigmoid(x_emb - d_i * acc)
    #pragma unroll
    for (int r = 0; r < 8; r++) {
        int gi = i0 + ri + r;
        float di = g_d[gi];
        const float* erow = E + (size_t)gi * HH + hj;
        float* orow = out + ((size_t)bs * NN + gi) * HH + hj;
        #pragma unroll
        for (int c4 = 0; c4 < 8; c4 += 4) {
            float4 ev = *(const float4*)(erow + c4);
            float4 ov;
            ov.x = 1.f / (1.f + __expf(-(ev.x - di * acc[r][c4 + 0])));
            ov.y = 1.f / (1.f + __expf(-(ev.y - di * acc[r][c4 + 1])));
            ov.z = 1.f / (1.f + __expf(-(ev.z - di * acc[r][c4 + 2])));
            ov.w = 1.f / (1.f + __expf(-(ev.w - di * acc[r][c4 + 3])));
            *(float4*)(orow + c4) = ov;
        }
    }
}

// ---------------------------------------------------------------------------
extern "C" void kernel_launch(void* const* d_in, const int* in_sizes, int n_in,
                              void* d_out, int out_size) {
    const float* x = (const float*)d_in[0];   // [4,12,4096,64]
    const float* A = (const float*)d_in[1];   // [4096,4096]
    const float* W = (const float*)d_in[2];   // [128,64]
    float* out = (float*)d_out;

    rowsum_kernel<<<NN, 256>>>(A);
    emb_kernel<<<(NBS * NN) / 32, 256>>>(x, W);
    gcn_gemm_kernel<<<dim3(NN / 128, NBS), 256>>>(A, out);

    // second tuple element: A passthrough
    if ((unsigned long long)out_size >= OUT_ELEMS + A_ELEMS) {
        cudaMemcpyAsync(out + OUT_ELEMS, A, A_ELEMS * sizeof(float),
                        cudaMemcpyDeviceToDevice);
    }
}

// round 5
// speedup vs baseline: 3.5160x; 3.5160x over previous
#include <cuda_runtime.h>
#include <cuda_bf16.h>
#include <stdint.h>
#include <math.h>

// Problem shapes (fixed by the dataset)
#define NN 4096          // graph nodes
#define CC 64            // input channels
#define HH 128           // embedding dim
#define NBS 48           // B*S
#define OUT_ELEMS (48ULL * 4096ULL * 128ULL)
#define A_ELEMS   (4096ULL * 4096ULL)

// Scratch (allocation-free rule: __device__ globals)
__device__ float g_d[NN];                                   // rsqrt(rowsum(A)+1)
__device__ float g_xemb[(size_t)NBS * NN * HH];             // E fp32 [bs][k][h]
__device__ __nv_bfloat16 g_abf[A_ELEMS];                    // A bf16
__device__ __nv_bfloat16 g_ebt[(size_t)NBS * HH * NN];      // bf16 d_k*E, [bs][h][k]

// ---------------------------------------------------------------------------
// helpers (arch-agnostic PTX only: ldmatrix / mma.sync / cp.async)
// ---------------------------------------------------------------------------
__device__ __forceinline__ uint32_t smem_u32(const void* p) {
    uint32_t a;
    asm("{ .reg .u64 t; cvta.to.shared.u64 t, %1; cvt.u32.u64 %0, t; }" : "=r"(a) : "l"(p));
    return a;
}
#define LDSM_X4(r, addr) \
    asm volatile("ldmatrix.sync.aligned.m8n8.x4.shared.b16 {%0,%1,%2,%3}, [%4];" \
        : "=r"((r)[0]), "=r"((r)[1]), "=r"((r)[2]), "=r"((r)[3]) : "r"(addr))

__device__ __forceinline__ void mma16816(float* c, const uint32_t* a, uint32_t b0, uint32_t b1) {
    asm volatile("mma.sync.aligned.m16n8k16.row.col.f32.bf16.bf16.f32 "
                 "{%0,%1,%2,%3}, {%4,%5,%6,%7}, {%8,%9}, {%0,%1,%2,%3};"
                 : "+f"(c[0]), "+f"(c[1]), "+f"(c[2]), "+f"(c[3])
                 : "r"(a[0]), "r"(a[1]), "r"(a[2]), "r"(a[3]), "r"(b0), "r"(b1));
}
#define CP_ASYNC16(saddr, gaddr) \
    asm volatile("cp.async.cg.shared.global [%0], [%1], 16;" :: "r"(saddr), "l"(gaddr))
#define CP_COMMIT() asm volatile("cp.async.commit_group;" ::: "memory")
#define CP_WAIT1()  asm volatile("cp.async.wait_group 1;" ::: "memory")
#define CP_WAIT0()  asm volatile("cp.async.wait_group 0;" ::: "memory")

// ---------------------------------------------------------------------------
// Kernel 1: d[i] = rsqrt(rowsum(A)+1)
// ---------------------------------------------------------------------------
__global__ void __launch_bounds__(256) rowsum_kernel(const float* __restrict__ A) {
    int row = blockIdx.x;
    const float* a = A + (size_t)row * NN;
    float s = 0.f;
    for (int k = threadIdx.x; k < NN; k += 256) s += a[k];
    #pragma unroll
    for (int o = 16; o > 0; o >>= 1) s += __shfl_down_sync(0xffffffffu, s, o);
    __shared__ float red[8];
    if ((threadIdx.x & 31) == 0) red[threadIdx.x >> 5] = s;
    __syncthreads();
    if (threadIdx.x == 0) {
        float t = 0.f;
        #pragma unroll
        for (int w = 0; w < 8; w++) t += red[w];
        g_d[row] = rsqrtf(t + 1.0f);
    }
}

// ---------------------------------------------------------------------------
// Kernel 2: A fp32 -> bf16
// ---------------------------------------------------------------------------
__global__ void __launch_bounds__(256) conv_a_kernel(const float* __restrict__ A) {
    size_t idx = ((size_t)blockIdx.x * 256 + threadIdx.x) * 8;
    float4 a = *(const float4*)(A + idx);
    float4 b = *(const float4*)(A + idx + 4);
    __nv_bfloat162* o = (__nv_bfloat162*)(g_abf + idx);
    o[0] = __floats2bfloat162_rn(a.x, a.y);
    o[1] = __floats2bfloat162_rn(a.z, a.w);
    o[2] = __floats2bfloat162_rn(b.x, b.y);
    o[3] = __floats2bfloat162_rn(b.z, b.w);
}

// ---------------------------------------------------------------------------
// Kernel 3: x_emb = x @ W^T -> E fp32 [bs][k][h] and bf16 d_k*E -> [bs][h][k]
// ---------------------------------------------------------------------------
__global__ void __launch_bounds__(256) emb_kernel(const float* __restrict__ x,
                                                  const float* __restrict__ W) {
    __shared__ __align__(16) char pool[41984];
    float (*Ws)[HH] = (float(*)[HH])pool;                 // 64x128 fp32
    float (*xs)[CC] = (float(*)[CC])(pool + 32768);       // 32x64 fp32

    int tid = threadIdx.x;
    int m0 = blockIdx.x * 32;
    int bs = m0 >> 12;
    int n0 = m0 & (NN - 1);

    #pragma unroll
    for (int r = 0; r < 32; r++) {
        int idx = tid + 256 * r;            // idx = h*64 + c
        Ws[idx & 63][idx >> 6] = W[idx];
    }
    #pragma unroll
    for (int j = 0; j < 2; j++) {
        int q = tid + 256 * j;
        int r = q >> 4;
        int c4 = (q & 15) * 4;
        *(float4*)(&xs[r][c4]) = *(const float4*)(x + (size_t)(m0 + r) * CC + c4);
    }
    __syncthreads();

    int r  = tid >> 3;
    int hb = (tid & 7) * 16;
    float acc[16];
    #pragma unroll
    for (int j = 0; j < 16; j++) acc[j] = 0.f;

    #pragma unroll 8
    for (int c = 0; c < CC; c++) {
        float xv = xs[r][c];
        #pragma unroll
        for (int j = 0; j < 16; j++) acc[j] += xv * Ws[c][hb + j];
    }

    float* orow = g_xemb + (size_t)(m0 + r) * HH + hb;
    #pragma unroll
    for (int j4 = 0; j4 < 16; j4 += 4)
        *(float4*)(orow + j4) = make_float4(acc[j4], acc[j4+1], acc[j4+2], acc[j4+3]);

    // bf16 d_k * E, transposed through smem
    float dk = g_d[n0 + r];
    __syncthreads();
    __nv_bfloat16 (*sht)[40] = (__nv_bfloat16(*)[40])pool;   // [128][40] padded
    #pragma unroll
    for (int j = 0; j < 16; j++)
        sht[hb + j][r] = __float2bfloat16(dk * acc[j]);
    __syncthreads();
    {
        int h = tid >> 1;
        int ko = (tid & 1) * 16;
        const uint4* src = (const uint4*)(&sht[h][ko]);
        uint4* dst = (uint4*)(g_ebt + ((size_t)bs * HH + h) * NN + n0 + ko);
        dst[0] = src[0];
        dst[1] = src[1];
    }
}

// ---------------------------------------------------------------------------
// Kernel 4: bf16 mma.sync GEMM + fused epilogue.
//   acc[i,h] = sum_k Abf[i,k] * (d_k*E)[h,k]     (both K-major)
//   out = sigmoid(E - d_i * acc)
// CTA: 128x128 tile, BK=64, cp.async double buffer, 8 warps of 64x32.
// ---------------------------------------------------------------------------
#define KPAD 72                                   // bf16 elems per smem row (144 B)
#define TILE_SM (128 * KPAD * 2)                  // 18432 B per operand tile
#define AOFF(buf) ((uint32_t)(buf) * 2u * TILE_SM)
#define BOFF(buf) (AOFF(buf) + TILE_SM)
#define GEMM_SMEM (4 * TILE_SM)                   // 73728 B

__device__ __forceinline__ void stage_tile(uint32_t sb,
                                           const __nv_bfloat16* __restrict__ gA,
                                           const __nv_bfloat16* __restrict__ gB,
                                           int k0, int buf, int tid) {
    #pragma unroll
    for (int j = 0; j < 4; j++) {
        int q = tid + 256 * j;               // 0..1023
        int row = q >> 3;                    // 0..127
        int c = q & 7;                       // 16B chunk
        uint32_t so = (uint32_t)(row * 144 + c * 16);
        CP_ASYNC16(sb + AOFF(buf) + so, gA + (size_t)row * NN + k0 + c * 8);
        CP_ASYNC16(sb + BOFF(buf) + so, gB + (size_t)row * NN + k0 + c * 8);
    }
}

__global__ void __launch_bounds__(256, 2) gcn_mma_kernel(float* __restrict__ out) {
    extern __shared__ __align__(16) char smem[];
    const uint32_t sb = smem_u32(smem);
    const int tid = threadIdx.x;
    const int wid = tid >> 5, lane = tid & 31;
    const int i0 = blockIdx.x * 128;
    const int bs = blockIdx.y;
    const int wm = (wid >> 2) * 64;          // warp row base within tile
    const int wn = (wid & 3) * 32;           // warp col base within tile

    const __nv_bfloat16* gA = g_abf + (size_t)i0 * NN;
    const __nv_bfloat16* gB = g_ebt + (size_t)bs * HH * NN;

    float c[4][4][4];
    #pragma unroll
    for (int mt = 0; mt < 4; mt++)
        #pragma unroll
        for (int nt = 0; nt < 4; nt++)
            #pragma unroll
            for (int r = 0; r < 4; r++) c[mt][nt][r] = 0.f;

    stage_tile(sb, gA, gB, 0, 0, tid);
    CP_COMMIT();

    const int NS = NN / 64;                  // 64 stages
    for (int s = 0; s < NS; s++) {
        const int cur = s & 1;
        if (s + 1 < NS) {
            stage_tile(sb, gA, gB, (s + 1) * 64, cur ^ 1, tid);
            CP_COMMIT();
            CP_WAIT1();
        } else {
            CP_WAIT0();
        }
        __syncthreads();

        const uint32_t sA = sb + AOFF(cur);
        const uint32_t sB = sb + BOFF(cur);
        #pragma unroll
        for (int kk = 0; kk < 4; kk++) {
            uint32_t a[4][4];
            #pragma unroll
            for (int mt = 0; mt < 4; mt++) {
                uint32_t addr = sA + (uint32_t)((wm + mt * 16 + (lane & 15)) * 144
                                                + (kk * 16 + (lane >> 4) * 8) * 2);
                LDSM_X4(a[mt], addr);
            }
            uint32_t b[2][4];
            #pragma unroll
            for (int nh = 0; nh < 2; nh++) {
                int nrow = wn + nh * 16 + (lane & 7) + ((lane >> 4) << 3);
                uint32_t addr = sB + (uint32_t)(nrow * 144
                                                + (kk * 16 + ((lane >> 3) & 1) * 8) * 2);
                LDSM_X4(b[nh], addr);
            }
            #pragma unroll
            for (int mt = 0; mt < 4; mt++)
                #pragma unroll
                for (int nt = 0; nt < 4; nt++)
                    mma16816(c[mt][nt], a[mt],
                             b[nt >> 1][(nt & 1) * 2], b[nt >> 1][(nt & 1) * 2 + 1]);
        }
        __syncthreads();
    }

    // fused epilogue: out = sigmoid(E - d_i * acc)
    #pragma unroll
    for (int mt = 0; mt < 4; mt++) {
        int r0 = i0 + wm + mt * 16 + (lane >> 2);
        int r1 = r0 + 8;
        float d0 = g_d[r0], d1 = g_d[r1];
        const float* e0 = g_xemb + ((size_t)bs * NN + r0) * HH;
        const float* e1 = g_xemb + ((size_t)bs * NN + r1) * HH;
        float* o0 = out + ((size_t)bs * NN + r0) * HH;
        float* o1 = out + ((size_t)bs * NN + r1) * HH;
        #pragma unroll
        for (int nt = 0; nt < 4; nt++) {
            int col = wn + nt * 8 + (lane & 3) * 2;
            float2 ea = *(const float2*)(e0 + col);
            float2 eb = *(const float2*)(e1 + col);
            float2 oa, ob;
            oa.x = 1.f / (1.f + __expf(-(ea.x - d0 * c[mt][nt][0])));
            oa.y = 1.f / (1.f + __expf(-(ea.y - d0 * c[mt][nt][1])));
            ob.x = 1.f / (1.f + __expf(-(eb.x - d1 * c[mt][nt][2])));
            ob.y = 1.f / (1.f + __expf(-(eb.y - d1 * c[mt][nt][3])));
            *(float2*)(o0 + col) = oa;
            *(float2*)(o1 + col) = ob;
        }
    }
}

// ---------------------------------------------------------------------------
extern "C" void kernel_launch(void* const* d_in, const int* in_sizes, int n_in,
                              void* d_out, int out_size) {
    const float* x = (const float*)d_in[0];   // [4,12,4096,64]
    const float* A = (const float*)d_in[1];   // [4096,4096]
    const float* W = (const float*)d_in[2];   // [128,64]
    float* out = (float*)d_out;

    cudaFuncSetAttribute(gcn_mma_kernel,
                         cudaFuncAttributeMaxDynamicSharedMemorySize, GEMM_SMEM);

    rowsum_kernel<<<NN, 256>>>(A);
    conv_a_kernel<<<A_ELEMS / (8 * 256), 256>>>(A);
    emb_kernel<<<(NBS * NN) / 32, 256>>>(x, W);            // needs g_d
    gcn_mma_kernel<<<dim3(NN / 128, NBS), 256, GEMM_SMEM>>>(out);

    // second tuple element: A passthrough
    if ((unsigned long long)out_size >= OUT_ELEMS + A_ELEMS) {
        cudaMemcpyAsync(out + OUT_ELEMS, A, A_ELEMS * sizeof(float),
                        cudaMemcpyDeviceToDevice);
    }
}

// round 13
// speedup vs baseline: 8.1357x; 2.3139x over previous
#include <cuda_runtime.h>
#include <cuda_bf16.h>
#include <stdint.h>
#include <math.h>

#define NN 4096
#define CC 64
#define HH 128
#define NBS 48
#define OUT_ELEMS (48ULL * 4096ULL * 128ULL)
#define A_ELEMS   (4096ULL * 4096ULL)

__device__ float g_d[NN];                                   // rsqrt(rowsum(A)+1)
__device__ float g_xemb[(size_t)NBS * NN * HH];             // E fp32 [bs][k][h]
__device__ __nv_bfloat16 g_abf[A_ELEMS];                    // A bf16
__device__ __nv_bfloat16 g_ebt[(size_t)NBS * HH * NN];      // bf16 d_k*E, [bs][h][k]

// ---------------------------------------------------------------------------
__device__ __forceinline__ uint32_t smem_u32(const void* p) {
    uint32_t a;
    asm("{ .reg .u64 t; cvta.to.shared.u64 t, %1; cvt.u32.u64 %0, t; }" : "=r"(a) : "l"(p));
    return a;
}
#define LDSM_X4(r, addr) \
    asm volatile("ldmatrix.sync.aligned.m8n8.x4.shared.b16 {%0,%1,%2,%3}, [%4];" \
        : "=r"((r)[0]), "=r"((r)[1]), "=r"((r)[2]), "=r"((r)[3]) : "r"(addr))
__device__ __forceinline__ void mma16816(float* c, const uint32_t* a, uint32_t b0, uint32_t b1) {
    asm volatile("mma.sync.aligned.m16n8k16.row.col.f32.bf16.bf16.f32 "
                 "{%0,%1,%2,%3}, {%4,%5,%6,%7}, {%8,%9}, {%0,%1,%2,%3};"
                 : "+f"(c[0]), "+f"(c[1]), "+f"(c[2]), "+f"(c[3])
                 : "r"(a[0]), "r"(a[1]), "r"(a[2]), "r"(a[3]), "r"(b0), "r"(b1));
}
#define CP_ASYNC16(saddr, gaddr) \
    asm volatile("cp.async.cg.shared.global [%0], [%1], 16;" :: "r"(saddr), "l"(gaddr))
#define CP_COMMIT() asm volatile("cp.async.commit_group;" ::: "memory")
#define CP_WAIT1()  asm volatile("cp.async.wait_group 1;" ::: "memory")
#define CP_WAIT0()  asm volatile("cp.async.wait_group 0;" ::: "memory")

// ---------------------------------------------------------------------------
// Kernel 1 (fused): one pass over A -> rowsum/d, bf16 A, fp32 passthrough.
// ---------------------------------------------------------------------------
__global__ void __launch_bounds__(256) rowpass_kernel(const float* __restrict__ A,
                                                      float* __restrict__ outA) {
    int row = blockIdx.x;
    const float4* a4 = (const float4*)(A + (size_t)row * NN);
    float4* o4 = (float4*)(outA + (size_t)row * NN);
    __nv_bfloat162* b2 = (__nv_bfloat162*)(g_abf + (size_t)row * NN);
    float s = 0.f;
    #pragma unroll
    for (int j = 0; j < 4; j++) {
        int idx = threadIdx.x + 256 * j;
        float4 v = a4[idx];
        o4[idx] = v;
        b2[idx * 2 + 0] = __floats2bfloat162_rn(v.x, v.y);
        b2[idx * 2 + 1] = __floats2bfloat162_rn(v.z, v.w);
        s += v.x + v.y + v.z + v.w;
    }
    #pragma unroll
    for (int o = 16; o > 0; o >>= 1) s += __shfl_down_sync(0xffffffffu, s, o);
    __shared__ float red[8];
    if ((threadIdx.x & 31) == 0) red[threadIdx.x >> 5] = s;
    __syncthreads();
    if (threadIdx.x == 0) {
        float t = 0.f;
        #pragma unroll
        for (int w = 0; w < 8; w++) t += red[w];
        g_d[row] = rsqrtf(t + 1.0f);
    }
}

// ---------------------------------------------------------------------------
// Kernel 2: emb v2. 32 node-rows per block, 256 threads.
// Thread (hq = tid&31, rseg = tid>>5): 4 rows x 4 h, float4 W reads
// (conflict-free), x reads are warp-wide broadcasts.
// Outputs: E fp32 [bs][k][h], ebt bf16 d_k*E [bs][h][k].
// ---------------------------------------------------------------------------
__global__ void __launch_bounds__(256) emb_kernel(const float* __restrict__ x,
                                                  const float* __restrict__ W) {
    __shared__ float Wt[CC][132];     // W^T padded: Wt[c][h]  (33792 B)
    __shared__ float xs[32][CC];      // 32 rows of x          (8192 B)

    const int tid = threadIdx.x;
    const int m0 = blockIdx.x * 32;
    const int bs = m0 >> 12;
    const int n0 = m0 & (NN - 1);

    // stage W^T  (8192 elems, coalesced gmem reads)
    #pragma unroll
    for (int r = 0; r < 32; r++) {
        int idx = tid + 256 * r;            // idx = h*64 + c
        Wt[idx & 63][idx >> 6] = W[idx];
    }
    // stage x (32 rows x 64)
    #pragma unroll
    for (int j = 0; j < 2; j++) {
        int q = tid + 256 * j;              // 0..511 float4s
        int r = q >> 4, c4 = (q & 15) * 4;
        *(float4*)(&xs[r][c4]) = *(const float4*)(x + (size_t)(m0 + r) * CC + c4);
    }
    __syncthreads();

    const int hq = tid & 31;                // h = hq*4
    const int rseg = tid >> 5;              // rows rseg*4..+3
    float acc[4][4];
    #pragma unroll
    for (int r = 0; r < 4; r++)
        #pragma unroll
        for (int j = 0; j < 4; j++) acc[r][j] = 0.f;

    #pragma unroll
    for (int c4 = 0; c4 < 16; c4++) {
        float4 w[4], xv[4];
        #pragma unroll
        for (int cc = 0; cc < 4; cc++)
            w[cc] = *(const float4*)(&Wt[c4 * 4 + cc][hq * 4]);   // lanes -> consecutive 16B
        #pragma unroll
        for (int r = 0; r < 4; r++)
            xv[r] = *(const float4*)(&xs[rseg * 4 + r][c4 * 4]);  // warp broadcast
        #pragma unroll
        for (int r = 0; r < 4; r++) {
            #pragma unroll
            for (int j = 0; j < 4; j++) {
                acc[r][j] += xv[r].x * ((const float*)&w[0])[j];
                acc[r][j] += xv[r].y * ((const float*)&w[1])[j];
                acc[r][j] += xv[r].z * ((const float*)&w[2])[j];
                acc[r][j] += xv[r].w * ((const float*)&w[3])[j];
            }
        }
    }

    // E fp32 out (coalesced across hq)
    #pragma unroll
    for (int r = 0; r < 4; r++) {
        float* orow = g_xemb + ((size_t)(m0 + rseg * 4 + r)) * HH + hq * 4;
        *(float4*)orow = make_float4(acc[r][0], acc[r][1], acc[r][2], acc[r][3]);
    }

    // bf16 d_k*E transposed -> [h][k] through smem (overlap onto Wt).
    // Row stride MUST be a multiple of 8 bf16 (16 B) for the uint4 reads below.
    __syncthreads();
    __nv_bfloat16 (*sht)[40] = (__nv_bfloat16(*)[40])Wt;   // [128][40] = 10240 B, 80B stride
    #pragma unroll
    for (int r = 0; r < 4; r++) {
        float dk = g_d[n0 + rseg * 4 + r];
        #pragma unroll
        for (int j = 0; j < 4; j++)
            sht[hq * 4 + j][rseg * 4 + r] = __float2bfloat16(dk * acc[r][j]);
    }
    __syncthreads();
    {
        int h = tid >> 1;
        int ko = (tid & 1) * 16;
        const uint4* src = (const uint4*)(&sht[h][ko]);    // 80*h + 2*ko : 16B-aligned
        uint4* dst = (uint4*)(g_ebt + ((size_t)bs * HH + h) * NN + n0 + ko);
        dst[0] = src[0];
        dst[1] = src[1];
    }
}

// ---------------------------------------------------------------------------
// Kernel 3: bf16 mma.sync GEMM + fused epilogue.
// 128x128 tile, BK=64, XOR-swizzled smem (no pad), 3-stage cp.async pipeline,
// one __syncthreads per stage. 8 warps of 64x32.
// ---------------------------------------------------------------------------
#define TILE_SM 16384u                            // 128 rows x 128 B
#define STAGE_SM (2u * TILE_SM)                   // A + B = 32 KB
#define GEMM_SMEM (3u * STAGE_SM)                 // 98304 B
#define AOFF(b) ((uint32_t)(b) * STAGE_SM)
#define BOFF(b) (AOFF(b) + TILE_SM)

__device__ __forceinline__ void stage_tile(uint32_t sb,
                                           const __nv_bfloat16* __restrict__ gA,
                                           const __nv_bfloat16* __restrict__ gB,
                                           int k0, int buf, int tid) {
    #pragma unroll
    for (int j = 0; j < 4; j++) {
        int q = tid + 256 * j;               // 0..1023 chunks (16B)
        int row = q >> 3;
        int c = q & 7;
        uint32_t so = (uint32_t)(row * 128 + ((c ^ (row & 7)) * 16));
        CP_ASYNC16(sb + AOFF(buf) + so, gA + (size_t)row * NN + k0 + c * 8);
        CP_ASYNC16(sb + BOFF(buf) + so, gB + (size_t)row * NN + k0 + c * 8);
    }
}

__global__ void __launch_bounds__(256, 2) gcn_mma_kernel(float* __restrict__ out) {
    extern __shared__ __align__(128) char smem[];
    const uint32_t sb = smem_u32(smem);
    const int tid = threadIdx.x;
    const int wid = tid >> 5, lane = tid & 31;
    const int i0 = blockIdx.x * 128;
    const int bs = blockIdx.y;
    const int wm = (wid >> 2) * 64;
    const int wn = (wid & 3) * 32;

    const __nv_bfloat16* gA = g_abf + (size_t)i0 * NN;
    const __nv_bfloat16* gB = g_ebt + (size_t)bs * HH * NN;

    float c[4][4][4];
    #pragma unroll
    for (int mt = 0; mt < 4; mt++)
        #pragma unroll
        for (int nt = 0; nt < 4; nt++)
            #pragma unroll
            for (int r = 0; r < 4; r++) c[mt][nt][r] = 0.f;

    stage_tile(sb, gA, gB, 0, 0, tid);  CP_COMMIT();
    stage_tile(sb, gA, gB, 64, 1, tid); CP_COMMIT();

    const int NS = NN / 64;
    for (int s = 0; s < NS; s++) {
        if (s + 1 < NS) CP_WAIT1(); else CP_WAIT0();
        __syncthreads();
        if (s + 2 < NS) { stage_tile(sb, gA, gB, (s + 2) * 64, (s + 2) % 3, tid); CP_COMMIT(); }

        const uint32_t sA = sb + AOFF(s % 3);
        const uint32_t sB = sb + BOFF(s % 3);
        #pragma unroll
        for (int kk = 0; kk < 4; kk++) {
            uint32_t a[4][4];
            #pragma unroll
            for (int mt = 0; mt < 4; mt++) {
                int row = wm + mt * 16 + (lane & 15);
                int ch  = kk * 2 + (lane >> 4);
                LDSM_X4(a[mt], sA + (uint32_t)(row * 128 + ((ch ^ (row & 7)) * 16)));
            }
            uint32_t b[2][4];
            #pragma unroll
            for (int nh = 0; nh < 2; nh++) {
                int nrow = wn + nh * 16 + (lane & 7) + ((lane >> 4) << 3);
                int ch   = kk * 2 + ((lane >> 3) & 1);
                LDSM_X4(b[nh], sB + (uint32_t)(nrow * 128 + ((ch ^ (nrow & 7)) * 16)));
            }
            #pragma unroll
            for (int mt = 0; mt < 4; mt++)
                #pragma unroll
                for (int nt = 0; nt < 4; nt++)
                    mma16816(c[mt][nt], a[mt],
                             b[nt >> 1][(nt & 1) * 2], b[nt >> 1][(nt & 1) * 2 + 1]);
        }
    }

    // fused epilogue: out = sigmoid(E - d_i * acc)
    #pragma unroll
    for (int mt = 0; mt < 4; mt++) {
        int r0 = i0 + wm + mt * 16 + (lane >> 2);
        int r1 = r0 + 8;
        float d0 = g_d[r0], d1 = g_d[r1];
        const float* e0 = g_xemb + ((size_t)bs * NN + r0) * HH;
        const float* e1 = g_xemb + ((size_t)bs * NN + r1) * HH;
        float* o0 = out + ((size_t)bs * NN + r0) * HH;
        float* o1 = out + ((size_t)bs * NN + r1) * HH;
        #pragma unroll
        for (int nt = 0; nt < 4; nt++) {
            int col = wn + nt * 8 + (lane & 3) * 2;
            float2 ea = *(const float2*)(e0 + col);
            float2 eb = *(const float2*)(e1 + col);
            float2 oa, ob;
            oa.x = 1.f / (1.f + __expf(-(ea.x - d0 * c[mt][nt][0])));
            oa.y = 1.f / (1.f + __expf(-(ea.y - d0 * c[mt][nt][1])));
            ob.x = 1.f / (1.f + __expf(-(eb.x - d1 * c[mt][nt][2])));
            ob.y = 1.f / (1.f + __expf(-(eb.y - d1 * c[mt][nt][3])));
            *(float2*)(o0 + col) = oa;
            *(float2*)(o1 + col) = ob;
        }
    }
}

// ---------------------------------------------------------------------------
extern "C" void kernel_launch(void* const* d_in, const int* in_sizes, int n_in,
                              void* d_out, int out_size) {
    const float* x = (const float*)d_in[0];
    const float* A = (const float*)d_in[1];
    const float* W = (const float*)d_in[2];
    float* out = (float*)d_out;

    cudaFuncSetAttribute(gcn_mma_kernel,
                         cudaFuncAttributeMaxDynamicSharedMemorySize, GEMM_SMEM);

    // fused: rowsum + bf16 convert + A passthrough (one read of A)
    rowpass_kernel<<<NN, 256>>>(A, out + OUT_ELEMS);
    emb_kernel<<<(NBS * NN) / 32, 256>>>(x, W);
    gcn_mma_kernel<<<dim3(NN / 128, NBS), 256, GEMM_SMEM>>>(out);
}